// round 1
// baseline (speedup 1.0000x reference)
#include <cuda_runtime.h>
#include <cuda_bf16.h>

// Problem constants (fixed shapes for this dataset)
#define BATCH   4
#define NPTS    16384
#define MPTS    4096
#define C1DIM   128
#define C2DIM   256
#define CIN     384       // C1 + C2
#define H1DIM   256
#define H2DIM   256
#define COUT    128
#define TOTAL   (BATCH * NPTS)   // 65536 points

// ---------------------------------------------------------------------------
// Scratch (static device globals — no runtime allocation allowed)
// ---------------------------------------------------------------------------
__device__ int   g_idx[TOTAL * 3];
__device__ float g_w[TOTAL * 3];
__device__ float g_X[(size_t)TOTAL * CIN];     // ~100 MB
__device__ float g_Ha[(size_t)TOTAL * H1DIM];  // ~67 MB
__device__ float g_Hb[(size_t)TOTAL * H2DIM];  // ~67 MB

// ---------------------------------------------------------------------------
// Kernel 1: three_nn + interpolation weights
// One block = 256 query points of one batch; xyz2 of that batch staged in smem.
// ---------------------------------------------------------------------------
__global__ __launch_bounds__(256) void three_nn_kernel(
    const float* __restrict__ xyz1, const float* __restrict__ xyz2)
{
    __shared__ float sx[MPTS];
    __shared__ float sy[MPTS];
    __shared__ float sz[MPTS];

    const int b = blockIdx.y;
    const float* p2 = xyz2 + (size_t)b * MPTS * 3;
    for (int j = threadIdx.x; j < MPTS; j += 256) {
        sx[j] = p2[3 * j + 0];
        sy[j] = p2[3 * j + 1];
        sz[j] = p2[3 * j + 2];
    }
    __syncthreads();

    const int n = blockIdx.x * 256 + threadIdx.x;
    const float* p1 = xyz1 + ((size_t)b * NPTS + n) * 3;
    const float x = p1[0], y = p1[1], z = p1[2];

    float d0 = 1e30f, d1 = 1e30f, d2 = 1e30f;
    int   i0 = 0, i1 = 0, i2 = 0;

#pragma unroll 4
    for (int j = 0; j < MPTS; j++) {
        float dx = x - sx[j];
        float dy = y - sy[j];
        float dz = z - sz[j];
        float d = dx * dx + dy * dy + dz * dz;
        if (d < d2) {
            if (d < d1) {
                d2 = d1; i2 = i1;
                if (d < d0) { d1 = d0; i1 = i0; d0 = d; i0 = j; }
                else        { d1 = d;  i1 = j; }
            } else {
                d2 = d; i2 = j;
            }
        }
    }

    float r0 = 1.0f / fmaxf(d0, 1e-10f);
    float r1 = 1.0f / fmaxf(d1, 1e-10f);
    float r2 = 1.0f / fmaxf(d2, 1e-10f);
    float s = 1.0f / (r0 + r1 + r2);

    size_t o = ((size_t)b * NPTS + n) * 3;
    g_idx[o + 0] = i0; g_idx[o + 1] = i1; g_idx[o + 2] = i2;
    g_w[o + 0] = r0 * s; g_w[o + 1] = r1 * s; g_w[o + 2] = r2 * s;
}

// ---------------------------------------------------------------------------
// Kernel 2: build X = concat(features1, three_interpolate(features2))
// One block per point; 384 threads = one output channel each.
// ---------------------------------------------------------------------------
__global__ __launch_bounds__(384) void build_x_kernel(
    const float* __restrict__ f1, const float* __restrict__ f2)
{
    const int p = blockIdx.x;     // 0 .. TOTAL-1
    const int t = threadIdx.x;    // 0 .. 383

    if (t < C1DIM) {
        g_X[(size_t)p * CIN + t] = f1[(size_t)p * C1DIM + t];
    } else {
        const int c = t - C1DIM;
        const int b = p >> 14;    // NPTS = 16384
        const size_t o = (size_t)p * 3;
        const int i0 = g_idx[o], i1 = g_idx[o + 1], i2 = g_idx[o + 2];
        const float w0 = g_w[o], w1 = g_w[o + 1], w2 = g_w[o + 2];
        const float* base = f2 + (size_t)b * MPTS * C2DIM;
        float v = w0 * base[(size_t)i0 * C2DIM + c]
                + w1 * base[(size_t)i1 * C2DIM + c]
                + w2 * base[(size_t)i2 * C2DIM + c];
        g_X[(size_t)p * CIN + C1DIM + c] = v;
    }
}

// ---------------------------------------------------------------------------
// Kernel 3: fp32 SGEMM with packed f32x2 FFMA, fused bias (+ optional ReLU)
// C[M,N] = A[M,K] @ W[K,N] + bias.  Block tile 64x128, thread tile 4x8.
// ---------------------------------------------------------------------------
__device__ __forceinline__ unsigned long long splat2(float a) {
    unsigned long long r;
    unsigned int u = __float_as_uint(a);
    asm("mov.b64 %0, {%1, %2};" : "=l"(r) : "r"(u), "r"(u));
    return r;
}
__device__ __forceinline__ void fma2(unsigned long long& d,
                                     unsigned long long a,
                                     unsigned long long b) {
    asm("fma.rn.f32x2 %0, %1, %2, %3;" : "=l"(d) : "l"(a), "l"(b), "l"(d));
}

__global__ __launch_bounds__(256, 2) void gemm_bias_act(
    const float* __restrict__ A, const float* __restrict__ W,
    const float* __restrict__ bias, float* __restrict__ C,
    int M, int K, int N, int doRelu)
{
    __shared__ __align__(16) float As[8][64];    // [k][m]
    __shared__ __align__(16) float Bs[8][128];   // [k][n]

    const int tid = threadIdx.x;
    const int tx = tid & 15;     // 0..15 -> 8 columns each
    const int ty = tid >> 4;     // 0..15 -> 4 rows each
    const int m0 = blockIdx.y * 64;
    const int n0 = blockIdx.x * 128;

    // Load mappings
    const int arow = tid >> 2;          // 0..63
    const int acol = (tid & 3) << 1;    // 0,2,4,6
    const int brow = tid >> 5;          // 0..7
    const int bcol = (tid & 31) << 2;   // 0..124

    const float* Ap = A + (size_t)(m0 + arow) * K + acol;
    const float* Wp = W + (size_t)brow * N + n0 + bcol;

    unsigned long long acc[4][4];
#pragma unroll
    for (int i = 0; i < 4; i++)
#pragma unroll
        for (int j = 0; j < 4; j++) acc[i][j] = 0ULL;  // (+0.f, +0.f)

    for (int k0 = 0; k0 < K; k0 += 8) {
        float2 av = *(const float2*)(Ap + k0);
        float4 bv = *(const float4*)(Wp + (size_t)k0 * N);
        As[acol][arow]     = av.x;
        As[acol + 1][arow] = av.y;
        *(float4*)&Bs[brow][bcol] = bv;
        __syncthreads();

#pragma unroll
        for (int k = 0; k < 8; k++) {
            float4 a = *(const float4*)&As[k][ty << 2];
            const float* brow_ptr = &Bs[k][tx << 3];
            ulonglong2 b01 = *(const ulonglong2*)brow_ptr;
            ulonglong2 b23 = *(const ulonglong2*)(brow_ptr + 4);
            unsigned long long a2[4];
            a2[0] = splat2(a.x); a2[1] = splat2(a.y);
            a2[2] = splat2(a.z); a2[3] = splat2(a.w);
            unsigned long long bb[4] = {b01.x, b01.y, b23.x, b23.y};
#pragma unroll
            for (int i = 0; i < 4; i++)
#pragma unroll
                for (int j = 0; j < 4; j++)
                    fma2(acc[i][j], a2[i], bb[j]);
        }
        __syncthreads();
    }

    // Epilogue: bias + optional ReLU, vectorized stores
    float bvals[8];
#pragma unroll
    for (int j = 0; j < 8; j++) bvals[j] = bias[n0 + (tx << 3) + j];

#pragma unroll
    for (int i = 0; i < 4; i++) {
        const int row = m0 + (ty << 2) + i;
        float* Cp = C + (size_t)row * N + n0 + (tx << 3);
        float outv[8];
#pragma unroll
        for (int j = 0; j < 4; j++) {
            float lo = __uint_as_float((unsigned)(acc[i][j] & 0xffffffffULL));
            float hi = __uint_as_float((unsigned)(acc[i][j] >> 32));
            lo += bvals[2 * j];
            hi += bvals[2 * j + 1];
            if (doRelu) { lo = fmaxf(lo, 0.0f); hi = fmaxf(hi, 0.0f); }
            outv[2 * j] = lo; outv[2 * j + 1] = hi;
        }
        *(float4*)Cp       = make_float4(outv[0], outv[1], outv[2], outv[3]);
        *(float4*)(Cp + 4) = make_float4(outv[4], outv[5], outv[6], outv[7]);
    }
}

// ---------------------------------------------------------------------------
// Launch
// ---------------------------------------------------------------------------
extern "C" void kernel_launch(void* const* d_in, const int* in_sizes, int n_in,
                              void* d_out, int out_size)
{
    const float* xyz1 = (const float*)d_in[0];
    const float* xyz2 = (const float*)d_in[1];
    const float* f1   = (const float*)d_in[2];
    const float* f2   = (const float*)d_in[3];
    const float* W1   = (const float*)d_in[4];
    const float* b1   = (const float*)d_in[5];
    const float* W2   = (const float*)d_in[6];
    const float* b2   = (const float*)d_in[7];
    const float* W3   = (const float*)d_in[8];
    const float* b3   = (const float*)d_in[9];
    float* out = (float*)d_out;

    void *xp, *hap, *hbp;
    cudaGetSymbolAddress(&xp,  g_X);
    cudaGetSymbolAddress(&hap, g_Ha);
    cudaGetSymbolAddress(&hbp, g_Hb);
    float* Xp  = (float*)xp;
    float* Hap = (float*)hap;
    float* Hbp = (float*)hbp;

    dim3 g1(NPTS / 256, BATCH);
    three_nn_kernel<<<g1, 256>>>(xyz1, xyz2);

    build_x_kernel<<<TOTAL, 384>>>(f1, f2);

    gemm_bias_act<<<dim3(H1DIM / 128, TOTAL / 64), 256>>>(Xp,  W1, b1, Hap, TOTAL, CIN,   H1DIM, 1);
    gemm_bias_act<<<dim3(H2DIM / 128, TOTAL / 64), 256>>>(Hap, W2, b2, Hbp, TOTAL, H1DIM, H2DIM, 1);
    gemm_bias_act<<<dim3(COUT  / 128, TOTAL / 64), 256>>>(Hbp, W3, b3, out, TOTAL, H2DIM, COUT,  0);
}

// round 2
// speedup vs baseline: 1.0497x; 1.0497x over previous
#include <cuda_runtime.h>
#include <cuda_bf16.h>

// Problem constants (fixed shapes for this dataset)
#define BATCH   4
#define NPTS    16384
#define MPTS    4096
#define C1DIM   128
#define C2DIM   256
#define CIN     384       // C1 + C2
#define H1DIM   256
#define H2DIM   256
#define COUT    128
#define TOTAL   (BATCH * NPTS)   // 65536 points

// ---------------------------------------------------------------------------
// Scratch (static device globals — no runtime allocation allowed)
// ---------------------------------------------------------------------------
__device__ int   g_idx[TOTAL * 3];
__device__ float g_w[TOTAL * 3];
__device__ float g_X[(size_t)TOTAL * CIN];     // ~100 MB
__device__ float g_Ha[(size_t)TOTAL * H1DIM];  // ~67 MB
__device__ float g_Hb[(size_t)TOTAL * H2DIM];  // ~67 MB

// ---------------------------------------------------------------------------
// Kernel 1: three_nn + interpolation weights
// One block = 256 query points of one batch; xyz2 of that batch staged in smem.
// ---------------------------------------------------------------------------
__global__ __launch_bounds__(256) void three_nn_kernel(
    const float* __restrict__ xyz1, const float* __restrict__ xyz2)
{
    __shared__ float sx[MPTS];
    __shared__ float sy[MPTS];
    __shared__ float sz[MPTS];

    const int b = blockIdx.y;
    const float* p2 = xyz2 + (size_t)b * MPTS * 3;
    for (int j = threadIdx.x; j < MPTS; j += 256) {
        sx[j] = p2[3 * j + 0];
        sy[j] = p2[3 * j + 1];
        sz[j] = p2[3 * j + 2];
    }
    __syncthreads();

    const int n = blockIdx.x * 256 + threadIdx.x;
    const float* p1 = xyz1 + ((size_t)b * NPTS + n) * 3;
    const float x = p1[0], y = p1[1], z = p1[2];

    float d0 = 1e30f, d1 = 1e30f, d2 = 1e30f;
    int   i0 = 0, i1 = 0, i2 = 0;

#pragma unroll 4
    for (int j = 0; j < MPTS; j++) {
        float dx = x - sx[j];
        float dy = y - sy[j];
        float dz = z - sz[j];
        float d = dx * dx + dy * dy + dz * dz;
        if (d < d2) {
            if (d < d1) {
                d2 = d1; i2 = i1;
                if (d < d0) { d1 = d0; i1 = i0; d0 = d; i0 = j; }
                else        { d1 = d;  i1 = j; }
            } else {
                d2 = d; i2 = j;
            }
        }
    }

    float r0 = 1.0f / fmaxf(d0, 1e-10f);
    float r1 = 1.0f / fmaxf(d1, 1e-10f);
    float r2 = 1.0f / fmaxf(d2, 1e-10f);
    float s = 1.0f / (r0 + r1 + r2);

    size_t o = ((size_t)b * NPTS + n) * 3;
    g_idx[o + 0] = i0; g_idx[o + 1] = i1; g_idx[o + 2] = i2;
    g_w[o + 0] = r0 * s; g_w[o + 1] = r1 * s; g_w[o + 2] = r2 * s;
}

// ---------------------------------------------------------------------------
// Kernel 2: build X = concat(features1, three_interpolate(features2))
// One block per point; 384 threads = one output channel each.
// ---------------------------------------------------------------------------
__global__ __launch_bounds__(384) void build_x_kernel(
    const float* __restrict__ f1, const float* __restrict__ f2)
{
    const int p = blockIdx.x;     // 0 .. TOTAL-1
    const int t = threadIdx.x;    // 0 .. 383

    if (t < C1DIM) {
        g_X[(size_t)p * CIN + t] = f1[(size_t)p * C1DIM + t];
    } else {
        const int c = t - C1DIM;
        const int b = p >> 14;    // NPTS = 16384
        const size_t o = (size_t)p * 3;
        const int i0 = g_idx[o], i1 = g_idx[o + 1], i2 = g_idx[o + 2];
        const float w0 = g_w[o], w1 = g_w[o + 1], w2 = g_w[o + 2];
        const float* base = f2 + (size_t)b * MPTS * C2DIM;
        float v = w0 * base[(size_t)i0 * C2DIM + c]
                + w1 * base[(size_t)i1 * C2DIM + c]
                + w2 * base[(size_t)i2 * C2DIM + c];
        g_X[(size_t)p * CIN + C1DIM + c] = v;
    }
}

// ---------------------------------------------------------------------------
// Kernel 3: fp32 SGEMM with packed f32x2 FFMA, fused bias (+ optional ReLU)
// C[M,N] = A[M,K] @ W[K,N] + bias.  Block tile 64x128, thread tile 4x8.
// ---------------------------------------------------------------------------
__device__ __forceinline__ unsigned long long splat2(float a) {
    unsigned long long r;
    unsigned int u = __float_as_uint(a);
    asm("mov.b64 %0, {%1, %2};" : "=l"(r) : "r"(u), "r"(u));
    return r;
}
__device__ __forceinline__ void fma2(unsigned long long& d,
                                     unsigned long long a,
                                     unsigned long long b) {
    asm("fma.rn.f32x2 %0, %1, %2, %3;" : "=l"(d) : "l"(a), "l"(b), "l"(d));
}

__global__ __launch_bounds__(256, 2) void gemm_bias_act(
    const float* __restrict__ A, const float* __restrict__ W,
    const float* __restrict__ bias, float* __restrict__ C,
    int M, int K, int N, int doRelu)
{
    __shared__ __align__(16) float As[8][64];    // [k][m]
    __shared__ __align__(16) float Bs[8][128];   // [k][n]

    const int tid = threadIdx.x;
    const int tx = tid & 15;     // 0..15 -> 8 columns each
    const int ty = tid >> 4;     // 0..15 -> 4 rows each
    const int m0 = blockIdx.y * 64;
    const int n0 = blockIdx.x * 128;

    // Load mappings
    const int arow = tid >> 2;          // 0..63
    const int acol = (tid & 3) << 1;    // 0,2,4,6
    const int brow = tid >> 5;          // 0..7
    const int bcol = (tid & 31) << 2;   // 0..124

    const float* Ap = A + (size_t)(m0 + arow) * K + acol;
    const float* Wp = W + (size_t)brow * N + n0 + bcol;

    unsigned long long acc[4][4];
#pragma unroll
    for (int i = 0; i < 4; i++)
#pragma unroll
        for (int j = 0; j < 4; j++) acc[i][j] = 0ULL;  // (+0.f, +0.f)

    for (int k0 = 0; k0 < K; k0 += 8) {
        float2 av = *(const float2*)(Ap + k0);
        float4 bv = *(const float4*)(Wp + (size_t)k0 * N);
        As[acol][arow]     = av.x;
        As[acol + 1][arow] = av.y;
        *(float4*)&Bs[brow][bcol] = bv;
        __syncthreads();

#pragma unroll
        for (int k = 0; k < 8; k++) {
            float4 a = *(const float4*)&As[k][ty << 2];
            const float* brow_ptr = &Bs[k][tx << 3];
            ulonglong2 b01 = *(const ulonglong2*)brow_ptr;
            ulonglong2 b23 = *(const ulonglong2*)(brow_ptr + 4);
            unsigned long long a2[4];
            a2[0] = splat2(a.x); a2[1] = splat2(a.y);
            a2[2] = splat2(a.z); a2[3] = splat2(a.w);
            unsigned long long bb[4] = {b01.x, b01.y, b23.x, b23.y};
#pragma unroll
            for (int i = 0; i < 4; i++)
#pragma unroll
                for (int j = 0; j < 4; j++)
                    fma2(acc[i][j], a2[i], bb[j]);
        }
        __syncthreads();
    }

    // Epilogue: bias + optional ReLU, vectorized stores
    float bvals[8];
#pragma unroll
    for (int j = 0; j < 8; j++) bvals[j] = bias[n0 + (tx << 3) + j];

#pragma unroll
    for (int i = 0; i < 4; i++) {
        const int row = m0 + (ty << 2) + i;
        float* Cp = C + (size_t)row * N + n0 + (tx << 3);
        float outv[8];
#pragma unroll
        for (int j = 0; j < 4; j++) {
            float lo = __uint_as_float((unsigned)(acc[i][j] & 0xffffffffULL));
            float hi = __uint_as_float((unsigned)(acc[i][j] >> 32));
            lo += bvals[2 * j];
            hi += bvals[2 * j + 1];
            if (doRelu) { lo = fmaxf(lo, 0.0f); hi = fmaxf(hi, 0.0f); }
            outv[2 * j] = lo; outv[2 * j + 1] = hi;
        }
        *(float4*)Cp       = make_float4(outv[0], outv[1], outv[2], outv[3]);
        *(float4*)(Cp + 4) = make_float4(outv[4], outv[5], outv[6], outv[7]);
    }
}

// ---------------------------------------------------------------------------
// Launch
// ---------------------------------------------------------------------------
extern "C" void kernel_launch(void* const* d_in, const int* in_sizes, int n_in,
                              void* d_out, int out_size)
{
    const float* xyz1 = (const float*)d_in[0];
    const float* xyz2 = (const float*)d_in[1];
    const float* f1   = (const float*)d_in[2];
    const float* f2   = (const float*)d_in[3];
    const float* W1   = (const float*)d_in[4];
    const float* b1   = (const float*)d_in[5];
    const float* W2   = (const float*)d_in[6];
    const float* b2   = (const float*)d_in[7];
    const float* W3   = (const float*)d_in[8];
    const float* b3   = (const float*)d_in[9];
    float* out = (float*)d_out;

    void *xp, *hap, *hbp;
    cudaGetSymbolAddress(&xp,  g_X);
    cudaGetSymbolAddress(&hap, g_Ha);
    cudaGetSymbolAddress(&hbp, g_Hb);
    float* Xp  = (float*)xp;
    float* Hap = (float*)hap;
    float* Hbp = (float*)hbp;

    dim3 g1(NPTS / 256, BATCH);
    three_nn_kernel<<<g1, 256>>>(xyz1, xyz2);

    build_x_kernel<<<TOTAL, 384>>>(f1, f2);

    gemm_bias_act<<<dim3(H1DIM / 128, TOTAL / 64), 256>>>(Xp,  W1, b1, Hap, TOTAL, CIN,   H1DIM, 1);
    gemm_bias_act<<<dim3(H2DIM / 128, TOTAL / 64), 256>>>(Hap, W2, b2, Hbp, TOTAL, H1DIM, H2DIM, 1);
    gemm_bias_act<<<dim3(COUT  / 128, TOTAL / 64), 256>>>(Hbp, W3, b3, out, TOTAL, H2DIM, COUT,  0);
}